// round 2
// baseline (speedup 1.0000x reference)
#include <cuda_runtime.h>
#include <math.h>

#define BS    8
#define NROT  60
#define NPTS  500
#define NBR   (BS * NROT)
#define HW    6400   // 80*80

// Scratch (allocation-free: __device__ globals)
__device__ float g_sym[NBR];
__device__ float g_nonsym[NBR];
__device__ float g_scal[2];   // [0] = loss_reg, [1] = loss_t

// ---------------------------------------------------------------------------
// Kernel 1: per-(b,r) symmetric/nonsymmetric chamfer distances.
// One block per (b, r). 256 threads; each thread owns pred points n and n+256.
// Inner pair cost: 3 FFMA + 1 FMNMX, target data broadcast from SMEM float4.
// ---------------------------------------------------------------------------
__global__ __launch_bounds__(256) void dist_kernel(
    const float* __restrict__ pred_r,        // (8,60,4)
    const float* __restrict__ model_points,  // (8,1,500,3)
    const float* __restrict__ target_r)      // (8,1,500,3)
{
    const int br = blockIdx.x;
    const int b  = br / NROT;

    __shared__ float4 tg[NPTS];     // (-2tx, -2ty, -2tz, |t|^2)
    __shared__ float  redA[256];
    __shared__ float  redB[256];

    const float* tp = target_r + (size_t)b * NPTS * 3;
    for (int m = threadIdx.x; m < NPTS; m += 256) {
        float tx = tp[3*m], ty = tp[3*m+1], tz = tp[3*m+2];
        tg[m] = make_float4(-2.f*tx, -2.f*ty, -2.f*tz, tx*tx + ty*ty + tz*tz);
    }

    // Rotation matrix R from (unnormalized) quaternion, exactly as reference.
    const float* q = pred_r + (size_t)br * 4;
    float w = q[0], x = q[1], y = q[2], z = q[3];
    float r00 = 1.f - 2.f*(y*y + z*z);
    float r01 = 2.f*x*y - 2.f*w*z;
    float r02 = 2.f*w*y + 2.f*x*z;
    float r10 = 2.f*x*y + 2.f*z*w;
    float r11 = 1.f - 2.f*(x*x + z*z);
    float r12 = -2.f*w*x + 2.f*y*z;
    float r20 = -2.f*w*y + 2.f*x*z;
    float r21 = 2.f*w*x + 2.f*y*z;
    float r22 = 1.f - 2.f*(x*x + y*y);

    __syncthreads();

    const float* mpb = model_points + (size_t)b * NPTS * 3;
    const int n0 = threadIdx.x;
    const int n1 = threadIdx.x + 256;
    const bool v1 = (n1 < NPTS);

    float m0x = mpb[3*n0], m0y = mpb[3*n0+1], m0z = mpb[3*n0+2];
    float p0x = r00*m0x + r01*m0y + r02*m0z;
    float p0y = r10*m0x + r11*m0y + r12*m0z;
    float p0z = r20*m0x + r21*m0y + r22*m0z;
    float a20 = p0x*p0x + p0y*p0y + p0z*p0z;

    float p1x = 0.f, p1y = 0.f, p1z = 0.f, a21 = 0.f;
    if (v1) {
        float m1x = mpb[3*n1], m1y = mpb[3*n1+1], m1z = mpb[3*n1+2];
        p1x = r00*m1x + r01*m1y + r02*m1z;
        p1y = r10*m1x + r11*m1y + r12*m1z;
        p1z = r20*m1x + r21*m1y + r22*m1z;
        a21 = p1x*p1x + p1y*p1y + p1z*p1z;
    }

    // min over m of (|t_m|^2 - 2 <p, t_m>); two accumulators break FMNMX chain.
    const float INF = 3.4e38f;
    float mn0a = INF, mn0b = INF, mn1a = INF, mn1b = INF;
    #pragma unroll 2
    for (int m = 0; m < NPTS; m += 2) {
        float4 ta = tg[m];
        float4 tb = tg[m+1];
        float s0a = fmaf(p0x, ta.x, fmaf(p0y, ta.y, fmaf(p0z, ta.z, ta.w)));
        float s1a = fmaf(p1x, ta.x, fmaf(p1y, ta.y, fmaf(p1z, ta.z, ta.w)));
        float s0b = fmaf(p0x, tb.x, fmaf(p0y, tb.y, fmaf(p0z, tb.z, tb.w)));
        float s1b = fmaf(p1x, tb.x, fmaf(p1y, tb.y, fmaf(p1z, tb.z, tb.w)));
        mn0a = fminf(mn0a, s0a);
        mn1a = fminf(mn1a, s1a);
        mn0b = fminf(mn0b, s0b);
        mn1b = fminf(mn1b, s1b);
    }
    float mn0 = fminf(mn0a, mn0b);
    float mn1 = fminf(mn1a, mn1b);

    float d0 = sqrtf(fmaxf(a20 + mn0, 1e-12f));
    float d1 = v1 ? sqrtf(fmaxf(a21 + mn1, 1e-12f)) : 0.f;

    // nonsym: ||p_n - t_n|| (recover t from tg: t = -0.5 * tg.xyz)
    float4 t0 = tg[n0];
    float dx0 = fmaf(0.5f, t0.x, p0x);
    float dy0 = fmaf(0.5f, t0.y, p0y);
    float dz0 = fmaf(0.5f, t0.z, p0z);
    float ns = sqrtf(dx0*dx0 + dy0*dy0 + dz0*dz0);
    if (v1) {
        float4 t1 = tg[n1];
        float dx1 = fmaf(0.5f, t1.x, p1x);
        float dy1 = fmaf(0.5f, t1.y, p1y);
        float dz1 = fmaf(0.5f, t1.z, p1z);
        ns += sqrtf(dx1*dx1 + dy1*dy1 + dz1*dz1);
    }

    // Block reductions (two sums in parallel).
    redA[threadIdx.x] = d0 + d1;
    redB[threadIdx.x] = ns;
    __syncthreads();
    for (int s = 128; s > 0; s >>= 1) {
        if (threadIdx.x < s) {
            redA[threadIdx.x] += redA[threadIdx.x + s];
            redB[threadIdx.x] += redB[threadIdx.x + s];
        }
        __syncthreads();
    }
    if (threadIdx.x == 0) {
        g_sym[br]    = redA[0] * (1.0f / NPTS);
        g_nonsym[br] = redB[0] * (1.0f / NPTS);
    }
}

// ---------------------------------------------------------------------------
// Kernel 2: regularization loss. One block of 512; threads 0..479 handle (b,r).
// ---------------------------------------------------------------------------
__global__ __launch_bounds__(512) void reg_kernel(
    const float* __restrict__ pred_r,       // (8,60,4)
    const float* __restrict__ rot_anchors)  // (60,4)
{
    __shared__ float anc[NROT * 4];
    __shared__ float red[512];
    for (int i = threadIdx.x; i < NROT * 4; i += 512) anc[i] = rot_anchors[i];
    __syncthreads();

    float val = 0.f;
    const int i = threadIdx.x;
    if (i < NBR) {
        int r = i % NROT;
        float q0 = pred_r[4*i], q1 = pred_r[4*i+1];
        float q2 = pred_r[4*i+2], q3 = pred_r[4*i+3];
        float mx = -3.4e38f, dg = 0.f;
        #pragma unroll 4
        for (int a = 0; a < NROT; a++) {
            float c = q0*anc[4*a] + q1*anc[4*a+1] + q2*anc[4*a+2] + q3*anc[4*a+3];
            mx = fmaxf(mx, c);
            if (a == r) dg = c;
        }
        float reg = mx - dg;
        val = (reg > 0.001f) ? reg : 0.f;
    }
    red[threadIdx.x] = val;
    __syncthreads();
    for (int s = 256; s > 0; s >>= 1) {
        if (threadIdx.x < s) red[threadIdx.x] += red[threadIdx.x + s];
        __syncthreads();
    }
    if (threadIdx.x == 0) g_scal[0] = red[0] * (1.0f / NBR);
}

// ---------------------------------------------------------------------------
// Kernel 3: huber translation loss. One block of 512 covering 12000 elems.
// ---------------------------------------------------------------------------
__global__ __launch_bounds__(512) void t_kernel(
    const float* __restrict__ pred_t,     // (8,500,3)
    const float* __restrict__ target_t,   // (8,3,80,80)
    const int*   __restrict__ choose)     // (8,500)
{
    __shared__ float red[512];
    float acc = 0.f;
    const int total = BS * NPTS * 3;
    for (int i = threadIdx.x; i < total; i += 512) {
        int b   = i / (NPTS * 3);
        int rem = i - b * (NPTS * 3);
        int n   = rem / 3;
        int k   = rem - 3 * n;
        int ch  = choose[b * NPTS + n];
        float tv = target_t[(size_t)b * 3 * HW + (size_t)k * HW + ch];
        float d  = pred_t[i] - tv;
        float ad = fabsf(d);
        acc += (ad < 1.f) ? 0.5f * d * d : (ad - 0.5f);
    }
    red[threadIdx.x] = acc;
    __syncthreads();
    for (int s = 256; s > 0; s >>= 1) {
        if (threadIdx.x < s) red[threadIdx.x] += red[threadIdx.x + s];
        __syncthreads();
    }
    if (threadIdx.x == 0) g_scal[1] = red[0] * (1.0f / total);
}

// ---------------------------------------------------------------------------
// Kernel 4: finalize loss_r and combine.
// NOTE: `symmetric` is a numpy bool input; the harness promotes it to int32.
// Read as int (nonzero == true).
// ---------------------------------------------------------------------------
__global__ __launch_bounds__(512) void final_kernel(
    const float* __restrict__ pred_c,     // (8,60)
    const int*   __restrict__ symmetric,  // (8,) bool promoted to int32
    const float* __restrict__ diameters,  // (8,)
    float*       __restrict__ out)        // 4 floats
{
    __shared__ float red[512];
    float val = 0.f;
    const int i = threadIdx.x;
    if (i < NBR) {
        int b = i / NROT;
        float d = (symmetric[b] != 0) ? g_sym[i] : g_nonsym[i];
        float c = pred_c[i];
        val = (d / (diameters[b] * c) + logf(c)) * (1.0f / NROT);
    }
    red[threadIdx.x] = val;
    __syncthreads();
    for (int s = 256; s > 0; s >>= 1) {
        if (threadIdx.x < s) red[threadIdx.x] += red[threadIdx.x + s];
        __syncthreads();
    }
    if (threadIdx.x == 0) {
        float lr   = red[0];
        float lreg = g_scal[0];
        float lt   = g_scal[1];
        out[0] = lr + 2.f * lreg + 5.f * lt;
        out[1] = lr;
        out[2] = lreg;
        out[3] = lt;
    }
}

// ---------------------------------------------------------------------------
// Launch. Input order: pred_t, pred_r, pred_c, target_r, target_t,
//                      model_points, choose, symmetric, diameters, rot_anchors
// ---------------------------------------------------------------------------
extern "C" void kernel_launch(void* const* d_in, const int* in_sizes, int n_in,
                              void* d_out, int out_size)
{
    const float* pred_t       = (const float*)d_in[0];
    const float* pred_r       = (const float*)d_in[1];
    const float* pred_c       = (const float*)d_in[2];
    const float* target_r     = (const float*)d_in[3];
    const float* target_t     = (const float*)d_in[4];
    const float* model_points = (const float*)d_in[5];
    const int*   choose       = (const int*)d_in[6];
    const int*   symmetric    = (const int*)d_in[7];
    const float* diameters    = (const float*)d_in[8];
    const float* rot_anchors  = (const float*)d_in[9];
    float* out = (float*)d_out;

    dist_kernel<<<NBR, 256>>>(pred_r, model_points, target_r);
    reg_kernel<<<1, 512>>>(pred_r, rot_anchors);
    t_kernel<<<1, 512>>>(pred_t, target_t, choose);
    final_kernel<<<1, 512>>>(pred_c, symmetric, diameters, out);
}

// round 3
// speedup vs baseline: 1.3616x; 1.3616x over previous
#include <cuda_runtime.h>
#include <math.h>

#define BS    8
#define NROT  60
#define NPTS  500
#define NBR   (BS * NROT)     // 480
#define HW    6400            // 80*80
#define NPAIR 250             // NPTS/2

typedef unsigned long long u64;

// Scratch (allocation-free: __device__ globals; zero-initialized at load)
__device__ float g_sym[NBR];
__device__ float g_nonsym[NBR];
__device__ float g_scal[2];       // [0] = loss_reg, [1] = loss_t
__device__ unsigned int g_cnt;    // completion counter (reset by last block)

// ---- f32x2 packed helpers (FFMA2 path; sm_103a) ----------------------------
__device__ __forceinline__ u64 pack2(float a, float b) {
    u64 r; asm("mov.b64 %0, {%1, %2};" : "=l"(r) : "f"(a), "f"(b)); return r;
}
__device__ __forceinline__ u64 fma2(u64 a, u64 b, u64 c) {
    u64 d; asm("fma.rn.f32x2 %0, %1, %2, %3;" : "=l"(d) : "l"(a), "l"(b), "l"(c));
    return d;
}
__device__ __forceinline__ void unpack2(u64 v, float& lo, float& hi) {
    asm("mov.b64 {%0, %1}, %2;" : "=f"(lo), "=f"(hi) : "l"(v));
}

// ---------------------------------------------------------------------------
// Single fused kernel, grid = NBR + 1 blocks of 128 threads.
//  blocks 0..479 : chamfer distances for one (b, r)
//  block  480    : reg loss + huber translation loss (concurrent)
//  last block to finish: finalize loss_r and combine into out[0..3]
// ---------------------------------------------------------------------------
__global__ __launch_bounds__(128) void fused_kernel(
    const float* __restrict__ pred_t,        // (8,500,3)
    const float* __restrict__ pred_r,        // (8,60,4)
    const float* __restrict__ pred_c,        // (8,60)
    const float* __restrict__ target_r,      // (8,1,500,3)
    const float* __restrict__ target_t,      // (8,3,80,80)
    const float* __restrict__ model_points,  // (8,1,500,3)
    const int*   __restrict__ choose,        // (8,500)
    const int*   __restrict__ symmetric,     // (8,) bool->int32
    const float* __restrict__ diameters,     // (8,)
    const float* __restrict__ rot_anchors,   // (60,4)
    float*       __restrict__ out)           // 4 floats
{
    __shared__ float4 sA[NPAIR];   // (-2tx[m0], -2tx[m1], -2ty[m0], -2ty[m1])
    __shared__ float4 sB[NPAIR];   // (-2tz[m0], -2tz[m1], |t0|^2,   |t1|^2)
    __shared__ float  redA[4], redB[4];
    __shared__ int    s_last;

    const int tid  = threadIdx.x;
    const int lane = tid & 31;
    const int wid  = tid >> 5;
    const int blk  = blockIdx.x;

    if (blk < NBR) {
        // ================= chamfer block =================
        const int b = blk / NROT;
        const float* tp = target_r + (size_t)b * NPTS * 3;

        for (int j = tid; j < NPAIR; j += 128) {
            int m0 = 2 * j, m1 = m0 + 1;
            float t0x = tp[3*m0], t0y = tp[3*m0+1], t0z = tp[3*m0+2];
            float t1x = tp[3*m1], t1y = tp[3*m1+1], t1z = tp[3*m1+2];
            sA[j] = make_float4(-2.f*t0x, -2.f*t1x, -2.f*t0y, -2.f*t1y);
            sB[j] = make_float4(-2.f*t0z, -2.f*t1z,
                                t0x*t0x + t0y*t0y + t0z*t0z,
                                t1x*t1x + t1y*t1y + t1z*t1z);
        }

        // Rotation matrix from (unnormalized) quaternion, as reference.
        const float* q = pred_r + (size_t)blk * 4;
        float w = q[0], x = q[1], y = q[2], z = q[3];
        float r00 = 1.f - 2.f*(y*y + z*z);
        float r01 = 2.f*x*y - 2.f*w*z;
        float r02 = 2.f*w*y + 2.f*x*z;
        float r10 = 2.f*x*y + 2.f*z*w;
        float r11 = 1.f - 2.f*(x*x + z*z);
        float r12 = -2.f*w*x + 2.f*y*z;
        float r20 = -2.f*w*y + 2.f*x*z;
        float r21 = 2.f*w*x + 2.f*y*z;
        float r22 = 1.f - 2.f*(x*x + y*y);

        __syncthreads();

        // 4 pred points per thread: n = tid + 128*i
        const float* mpb = model_points + (size_t)b * NPTS * 3;
        float px[4], py[4], pz[4], a2[4];
        bool  val[4];
        u64   PX[4], PY[4], PZ[4];
        #pragma unroll
        for (int i = 0; i < 4; i++) {
            int n = tid + 128 * i;
            val[i] = (n < NPTS);
            float mx = 0.f, my = 0.f, mz = 0.f;
            if (val[i]) { mx = mpb[3*n]; my = mpb[3*n+1]; mz = mpb[3*n+2]; }
            px[i] = r00*mx + r01*my + r02*mz;
            py[i] = r10*mx + r11*my + r12*mz;
            pz[i] = r20*mx + r21*my + r22*mz;
            a2[i] = px[i]*px[i] + py[i]*py[i] + pz[i]*pz[i];
            PX[i] = pack2(px[i], px[i]);
            PY[i] = pack2(py[i], py[i]);
            PZ[i] = pack2(pz[i], pz[i]);
        }

        const float INF = 3.4e38f;
        float mnlo[4] = {INF, INF, INF, INF};
        float mnhi[4] = {INF, INF, INF, INF};

        #pragma unroll 5
        for (int j = 0; j < NPAIR; j++) {
            ulonglong2 va = *reinterpret_cast<const ulonglong2*>(&sA[j]); // X, Y
            ulonglong2 vb = *reinterpret_cast<const ulonglong2*>(&sB[j]); // Z, W
            #pragma unroll
            for (int i = 0; i < 4; i++) {
                u64 s = fma2(PX[i], va.x, fma2(PY[i], va.y, fma2(PZ[i], vb.x, vb.y)));
                float lo, hi; unpack2(s, lo, hi);
                mnlo[i] = fminf(mnlo[i], lo);
                mnhi[i] = fminf(mnhi[i], hi);
            }
        }

        float symsum = 0.f, nssum = 0.f;
        #pragma unroll
        for (int i = 0; i < 4; i++) {
            if (val[i]) {
                float mn = fminf(mnlo[i], mnhi[i]);
                symsum += sqrtf(fmaxf(a2[i] + mn, 1e-12f));
                int n = tid + 128 * i;
                float dx = px[i] - tp[3*n];
                float dy = py[i] - tp[3*n+1];
                float dz = pz[i] - tp[3*n+2];
                nssum += sqrtf(dx*dx + dy*dy + dz*dz);
            }
        }

        #pragma unroll
        for (int off = 16; off; off >>= 1) {
            symsum += __shfl_down_sync(0xffffffffu, symsum, off);
            nssum  += __shfl_down_sync(0xffffffffu, nssum,  off);
        }
        if (lane == 0) { redA[wid] = symsum; redB[wid] = nssum; }
        __syncthreads();
        if (tid == 0) {
            float sA4 = redA[0] + redA[1] + redA[2] + redA[3];
            float sB4 = redB[0] + redB[1] + redB[2] + redB[3];
            g_sym[blk]    = sA4 * (1.0f / NPTS);
            g_nonsym[blk] = sB4 * (1.0f / NPTS);
        }
    } else {
        // ================= reg + huber block =================
        float* anc = reinterpret_cast<float*>(sA);  // 240 floats
        for (int i = tid; i < NROT * 4; i += 128) anc[i] = rot_anchors[i];
        __syncthreads();

        float regsum = 0.f;
        for (int i = tid; i < NBR; i += 128) {
            int r = i % NROT;
            float q0 = pred_r[4*i], q1 = pred_r[4*i+1];
            float q2 = pred_r[4*i+2], q3 = pred_r[4*i+3];
            float mx = -3.4e38f, dg = 0.f;
            #pragma unroll 4
            for (int a = 0; a < NROT; a++) {
                float c = q0*anc[4*a] + q1*anc[4*a+1] + q2*anc[4*a+2] + q3*anc[4*a+3];
                mx = fmaxf(mx, c);
                if (a == r) dg = c;
            }
            float reg = mx - dg;
            regsum += (reg > 0.001f) ? reg : 0.f;
        }

        float tsum = 0.f;
        for (int i = tid; i < BS * NPTS; i += 128) {
            int b  = i / NPTS;
            int ch = choose[i];
            const float* tb = target_t + (size_t)b * 3 * HW;
            float tv0 = tb[ch], tv1 = tb[HW + ch], tv2 = tb[2*HW + ch];
            float p0 = pred_t[3*i], p1 = pred_t[3*i+1], p2 = pred_t[3*i+2];
            float d0 = p0 - tv0, d1 = p1 - tv1, d2 = p2 - tv2;
            float a0 = fabsf(d0), a1 = fabsf(d1), a2v = fabsf(d2);
            tsum += (a0 < 1.f) ? 0.5f*d0*d0 : (a0 - 0.5f);
            tsum += (a1 < 1.f) ? 0.5f*d1*d1 : (a1 - 0.5f);
            tsum += (a2v < 1.f) ? 0.5f*d2*d2 : (a2v - 0.5f);
        }

        #pragma unroll
        for (int off = 16; off; off >>= 1) {
            regsum += __shfl_down_sync(0xffffffffu, regsum, off);
            tsum   += __shfl_down_sync(0xffffffffu, tsum,   off);
        }
        if (lane == 0) { redA[wid] = regsum; redB[wid] = tsum; }
        __syncthreads();
        if (tid == 0) {
            g_scal[0] = (redA[0]+redA[1]+redA[2]+redA[3]) * (1.0f / NBR);
            g_scal[1] = (redB[0]+redB[1]+redB[2]+redB[3]) * (1.0f / (BS*NPTS*3));
        }
    }

    // ================= grid-completion: last block finalizes =================
    __threadfence();
    if (tid == 0) {
        unsigned int ticket = atomicAdd(&g_cnt, 1u);
        s_last = (ticket == (unsigned)(NBR + 1) - 1u) ? 1 : 0;
    }
    __syncthreads();

    if (s_last) {
        float lr = 0.f;
        for (int i = tid; i < NBR; i += 128) {
            int b = i / NROT;
            float d = (symmetric[b] != 0) ? g_sym[i] : g_nonsym[i];
            float c = pred_c[i];
            lr += (d / (diameters[b] * c) + logf(c)) * (1.0f / NROT);
        }
        #pragma unroll
        for (int off = 16; off; off >>= 1)
            lr += __shfl_down_sync(0xffffffffu, lr, off);
        if (lane == 0) redA[wid] = lr;
        __syncthreads();
        if (tid == 0) {
            float lrt  = redA[0] + redA[1] + redA[2] + redA[3];
            float lreg = g_scal[0];
            float lt   = g_scal[1];
            out[0] = lrt + 2.f * lreg + 5.f * lt;
            out[1] = lrt;
            out[2] = lreg;
            out[3] = lt;
            g_cnt = 0;   // reset for next graph replay
        }
    }
}

// ---------------------------------------------------------------------------
// Launch. Input order: pred_t, pred_r, pred_c, target_r, target_t,
//                      model_points, choose, symmetric, diameters, rot_anchors
// ---------------------------------------------------------------------------
extern "C" void kernel_launch(void* const* d_in, const int* in_sizes, int n_in,
                              void* d_out, int out_size)
{
    fused_kernel<<<NBR + 1, 128>>>(
        (const float*)d_in[0], (const float*)d_in[1], (const float*)d_in[2],
        (const float*)d_in[3], (const float*)d_in[4], (const float*)d_in[5],
        (const int*)d_in[6],   (const int*)d_in[7],   (const float*)d_in[8],
        (const float*)d_in[9], (float*)d_out);
}